// round 14
// baseline (speedup 1.0000x reference)
#include <cuda_runtime.h>
#include <cstdint>

#define TT 4096
#define EE 256
#define HD 256
#define HH 512
#define NT 16
#define START_TAG 14
#define STOP_TAG 15
#define NEGV -10000.0f

// ---------------- scratch (static __device__, no allocation) ----------------
__device__ float g_x[TT * EE];            // gathered embeddings [T,E]
__device__ float g_Xp[2][TT * 1024];      // x@Wih^T + bih + bhh per dir  [T,1024]
__device__ float g_hid[TT * HH];          // [T,512] concat(hf,hb)
__device__ float g_tmp[TT * HH];          // tanh(hid @ w_omega)
__device__ float g_logits[TT];
__device__ float g_alpha[TT];
__device__ float g_feats[TT * NT];

// ---------------- helpers ----------------
__device__ __forceinline__ unsigned long long ffma2(unsigned long long a,
                                                    unsigned long long b,
                                                    unsigned long long c) {
    unsigned long long d;
    asm("fma.rn.f32x2 %0, %1, %2, %3;" : "=l"(d) : "l"(a), "l"(b), "l"(c));
    return d;
}
__device__ __forceinline__ float2 unpack2(unsigned long long a) {
    float2 u;
    asm("mov.b64 {%0,%1}, %2;" : "=f"(u.x), "=f"(u.y) : "l"(a));
    return u;
}
__device__ __forceinline__ uint32_t smem_u32(const void* p) {
    return (uint32_t)__cvta_generic_to_shared(p);
}
__device__ __forceinline__ void cluster_sync_all() {
    asm volatile("barrier.cluster.arrive.aligned;" ::: "memory");
    asm volatile("barrier.cluster.wait.aligned;" ::: "memory");
}
__device__ __forceinline__ void st_cluster_f32x2(uint32_t laddr, int peer, float v0, float v1) {
    asm volatile(
        "{\n\t.reg .u32 ra;\n\t"
        "mapa.shared::cluster.u32 ra, %0, %1;\n\t"
        "st.shared::cluster.v2.f32 [ra], {%2, %3};\n\t}"
        :: "r"(laddr), "r"(peer), "f"(v0), "f"(v1) : "memory");
}
// fast tanh: MUFU.EX2/RCP based, rel err ~2^-22.
__device__ __forceinline__ float fast_tanh(float x) {
    float xc = fminf(fmaxf(x, -9.f), 9.f);   // tanh(+-9) == 1 to fp32 eps
    float e = __expf(2.f * xc);
    return __fdividef(e - 1.f, e + 1.f);
}

// ---------------- 1. gather embeddings ----------------
__global__ void gather_emb(const int* __restrict__ sent, const float* __restrict__ emb) {
    int t = blockIdx.x;
    int e = threadIdx.x;
    g_x[t * EE + e] = emb[(size_t)sent[t] * EE + e];
}

// ---------------- 2. input projection: Xp = X @ Wih^T + bih + bhh ----------------
#define BM 64
#define BN 64
#define BK 16
__global__ void gemm_nt_bias(const float* __restrict__ Wf, const float* __restrict__ Wb,
                             const float* __restrict__ bihf, const float* __restrict__ bhhf,
                             const float* __restrict__ bihb, const float* __restrict__ bhhb) {
    const int dir = blockIdx.z;
    const float* B = dir ? Wb : Wf;
    const float* b1 = dir ? bihb : bihf;
    const float* b2 = dir ? bhhb : bhhf;
    float* C = g_Xp[dir];
    const float* A = g_x;
    const int K = EE, N = 1024;
    __shared__ float As[BK][BM + 4];
    __shared__ float Bs[BK][BN + 4];
    int tid = threadIdx.x;
    int tx = tid & 15, ty = tid >> 4;
    int by = blockIdx.y * BM, bx = blockIdx.x * BN;
    float acc[4][4] = {};
    for (int k0 = 0; k0 < K; k0 += BK) {
#pragma unroll
        for (int l = 0; l < 4; l++) {
            int e = tid + 256 * l;
            int m = e >> 4, kk = e & 15;
            As[kk][m] = A[(by + m) * K + k0 + kk];
            Bs[kk][m] = B[(bx + m) * K + k0 + kk];
        }
        __syncthreads();
#pragma unroll
        for (int kk = 0; kk < BK; kk++) {
            float ra[4], rb[4];
#pragma unroll
            for (int i = 0; i < 4; i++) ra[i] = As[kk][ty * 4 + i];
#pragma unroll
            for (int j = 0; j < 4; j++) rb[j] = Bs[kk][tx * 4 + j];
#pragma unroll
            for (int i = 0; i < 4; i++)
#pragma unroll
                for (int j = 0; j < 4; j++) acc[i][j] = fmaf(ra[i], rb[j], acc[i][j]);
        }
        __syncthreads();
    }
#pragma unroll
    for (int j = 0; j < 4; j++) {
        int c = bx + tx * 4 + j;
        float bb = b1[c] + b2[c];
#pragma unroll
        for (int i = 0; i < 4; i++)
            C[(size_t)(by + ty * 4 + i) * N + c] = acc[i][j] + bb;
    }
}

// ---------------- 3. LSTM recurrence: 2 clusters of 8 CTAs --------------------------
// CTA (rank r, dir d) owns hidden units [r*32, r*32+32).
// Matvec: 512 threads, lr = tid>>2 = local gate row (gate = lr>>5, unit = lr&31),
// q = tid&3 covers k-pairs q+4i (conflict-free LDS.64, 4-way broadcast).
// Gates stored UNIT-MAJOR: gsh2[ul*4 + gate] (bank-conflict-free both sides).
// Activation: warps 0-3; warp w owns units 8w..8w+7. Each of 32 lanes evaluates
// exactly ONE activation via sigmoid(x)=0.5*tanh(x/2)+0.5 (uniform MUFU chain).
// Lanes 0-7 gather si/sf/tg/so by shfl, run c-update + tanh, then pairwise
// float2 DSMEM broadcast. cluster.sync per step (frozen: 3 redesigns lost to it).
__global__ void __cluster_dims__(8, 1, 1) lstm_kernel(
    const float* __restrict__ Whh_f, const float* __restrict__ Whh_b,
    const float* __restrict__ h0, const float* __restrict__ c0) {
    __shared__ __align__(16) float hbuf[2][HD];
    __shared__ float gsh2[128];               // [ul*4 + gate]
    const int tid = threadIdx.x;
    const int dir = blockIdx.x >> 3;
    uint32_t crank;
    asm("mov.u32 %0, %%cluster_ctarank;" : "=r"(crank));
    const int lr = tid >> 2, q = tid & 3;
    const int gi = lr >> 5, ul = lr & 31;
    const int u = (int)crank * 32 + ul;
    const int grow = gi * 256 + u;
    const float* Whh = dir ? Whh_b : Whh_f;
    const float* Xp = g_Xp[dir];

    // activation-phase indices (warps 0-3)
    const int w = tid >> 5, lane = tid & 31;
    const int g_r = lane >> 3;                 // gate handled by this lane
    const int ul_r = 8 * w + (lane & 7);       // local unit handled (warps 0-3)
    const int uact = (int)crank * 32 + ul_r;   // global unit (lanes 0-7 own it)

    // preload weights: 32 f32x2 pairs, k-interleaved by q
    unsigned long long w2[32];
    const unsigned long long* wr = (const unsigned long long*)(Whh + (size_t)grow * HD);
#pragma unroll
    for (int i = 0; i < 32; i++) w2[i] = __ldg(wr + q + 4 * i);

    if (tid < HD) hbuf[0][tid] = h0[dir * HD + tid];
    float creg = 0.f;
    if (w < 4 && lane < 8) creg = c0[dir * HD + uact];
    __syncthreads();
    cluster_sync_all();   // initial hbuf visible cluster-wide

    for (int s = 0; s < TT; s++) {
        int tg = dir ? (TT - 1 - s) : s;
        float xg = __ldg(&Xp[(size_t)tg * 1024 + grow]);
        int buf = s & 1;
        const unsigned long long* hb = (const unsigned long long*)hbuf[buf];
        unsigned long long a0 = 0, a1 = 0;
#pragma unroll
        for (int i = 0; i < 32; i += 2) {
            a0 = ffma2(w2[i], hb[q + 4 * i], a0);
            a1 = ffma2(w2[i + 1], hb[q + 4 * (i + 1)], a1);
        }
        float2 f0 = unpack2(a0), f1 = unpack2(a1);
        float acc = (f0.x + f0.y) + (f1.x + f1.y);
        acc += __shfl_down_sync(0xFFFFFFFFu, acc, 2);
        acc += __shfl_down_sync(0xFFFFFFFFu, acc, 1);
        if (q == 0) gsh2[ul * 4 + gi] = acc + xg;
        __syncthreads();
        if (w < 4) {
            // one activation per lane: gates i,f,o -> sigmoid, gate g -> tanh
            float v = gsh2[ul_r * 4 + g_r];
            float xs = (g_r == 2) ? v : 0.5f * v;
            float xc = fminf(fmaxf(xs, -9.f), 9.f);
            float e = __expf(2.f * xc);
            float tt = __fdividef(e - 1.f, e + 1.f);
            float val = (g_r == 2) ? tt : fmaf(0.5f, tt, 0.5f);
            // gather the 4 gate values of this unit onto lanes 0-7
            float sfv = __shfl_sync(0xFFFFFFFFu, val, lane + 8);
            float tgv = __shfl_sync(0xFFFFFFFFu, val, lane + 16);
            float sov = __shfl_sync(0xFFFFFFFFu, val, lane + 24);
            float h = 0.f;
            if (lane < 8) {
                creg = sfv * creg + val * tgv;
                h = sov * fast_tanh(creg);
            }
            float h1 = __shfl_down_sync(0xFFFFFFFFu, h, 1);
            if (lane < 8) {
                if ((lane & 1) == 0) {
                    uint32_t dst = smem_u32(&hbuf[buf ^ 1][uact]);
#pragma unroll
                    for (int peer = 0; peer < 8; peer++) st_cluster_f32x2(dst, peer, h, h1);
                }
                g_hid[(size_t)tg * HH + dir * HD + uact] = h;
            }
        }
        cluster_sync_all();
    }
}

// ---------------- 4. attention GEMM: tmp = tanh(hid @ w_omega) ----------------
__global__ void gemm_nn_tanh(const float* __restrict__ B) {
    const float* A = g_hid;
    float* C = g_tmp;
    const int K = HH, N = HH;
    __shared__ float As[BK][BM + 4];
    __shared__ float Bs[BK][BN + 4];
    int tid = threadIdx.x;
    int tx = tid & 15, ty = tid >> 4;
    int by = blockIdx.y * BM, bx = blockIdx.x * BN;
    float acc[4][4] = {};
    for (int k0 = 0; k0 < K; k0 += BK) {
#pragma unroll
        for (int l = 0; l < 4; l++) {
            int e = tid + 256 * l;
            int m = e >> 4, kk = e & 15;
            As[kk][m] = A[(size_t)(by + m) * K + k0 + kk];
            int n = e & 63, kb = e >> 6;
            Bs[kb][n] = B[(size_t)(k0 + kb) * N + bx + n];
        }
        __syncthreads();
#pragma unroll
        for (int kk = 0; kk < BK; kk++) {
            float ra[4], rb[4];
#pragma unroll
            for (int i = 0; i < 4; i++) ra[i] = As[kk][ty * 4 + i];
#pragma unroll
            for (int j = 0; j < 4; j++) rb[j] = Bs[kk][tx * 4 + j];
#pragma unroll
            for (int i = 0; i < 4; i++)
#pragma unroll
                for (int j = 0; j < 4; j++) acc[i][j] = fmaf(ra[i], rb[j], acc[i][j]);
        }
        __syncthreads();
    }
#pragma unroll
    for (int i = 0; i < 4; i++)
#pragma unroll
        for (int j = 0; j < 4; j++)
            C[(size_t)(by + ty * 4 + i) * N + bx + tx * 4 + j] = tanhf(acc[i][j]);
}

// ---------------- 5. logits[t] = tmp[t,:] . u_omega ----------------
__global__ void logits_kernel(const float* __restrict__ u_omega) {
    int t = blockIdx.x;
    int tid = threadIdx.x;  // 256
    float p = g_tmp[(size_t)t * HH + tid] * u_omega[tid]
            + g_tmp[(size_t)t * HH + 256 + tid] * u_omega[256 + tid];
#pragma unroll
    for (int o = 16; o; o >>= 1) p += __shfl_down_sync(0xFFFFFFFFu, p, o);
    __shared__ float ws[8];
    if ((tid & 31) == 0) ws[tid >> 5] = p;
    __syncthreads();
    if (tid < 8) {
        float v = ws[tid];
#pragma unroll
        for (int o = 4; o; o >>= 1) v += __shfl_down_sync(0xFFu, v, o);
        if (tid == 0) g_logits[t] = v;
    }
}

// ---------------- 6. softmax over T ----------------
__global__ void softmax_kernel() {
    __shared__ float red[32];
    __shared__ float red2[32];
    int tid = threadIdx.x;  // 1024
    float m = -3.4e38f;
    for (int t = tid; t < TT; t += 1024) m = fmaxf(m, g_logits[t]);
#pragma unroll
    for (int o = 16; o; o >>= 1) m = fmaxf(m, __shfl_xor_sync(0xFFFFFFFFu, m, o));
    if ((tid & 31) == 0) red[tid >> 5] = m;
    __syncthreads();
    if (tid < 32) {
        float v = red[tid];
#pragma unroll
        for (int o = 16; o; o >>= 1) v = fmaxf(v, __shfl_xor_sync(0xFFFFFFFFu, v, o));
        red[tid] = v;
    }
    __syncthreads();
    m = red[0];
    float s = 0.f;
    for (int t = tid; t < TT; t += 1024) {
        float e = expf(g_logits[t] - m);
        g_alpha[t] = e;
        s += e;
    }
#pragma unroll
    for (int o = 16; o; o >>= 1) s += __shfl_xor_sync(0xFFFFFFFFu, s, o);
    if ((tid & 31) == 0) red2[tid >> 5] = s;
    __syncthreads();
    if (tid < 32) {
        float v = red2[tid];
#pragma unroll
        for (int o = 16; o; o >>= 1) v += __shfl_xor_sync(0xFFFFFFFFu, v, o);
        red2[tid] = v;
    }
    __syncthreads();
    float inv = 1.f / red2[0];
    for (int t = tid; t < TT; t += 1024) g_alpha[t] *= inv;
}

// ---------------- 7. feats = (alpha*hid) @ W_tag^T + b_tag ----------------
__global__ void feats_kernel(const float* __restrict__ Wtag, const float* __restrict__ btag) {
    int t = blockIdx.x;
    int tid = threadIdx.x;  // 512
    __shared__ float s[HH];
    float al = g_alpha[t];
    s[tid] = g_hid[(size_t)t * HH + tid] * al;
    __syncthreads();
    int w = tid >> 5, lane = tid & 31;  // 16 warps = 16 tags
    float acc = 0.f;
    const float* wt = Wtag + w * HH;
#pragma unroll 4
    for (int k = lane; k < HH; k += 32) acc = fmaf(s[k], wt[k], acc);
#pragma unroll
    for (int o = 16; o; o >>= 1) acc += __shfl_down_sync(0xFFFFFFFFu, acc, o);
    if (lane == 0) g_feats[t * NT + w] = acc + btag[w];
}

// ---------------- 8. Viterbi: single warp, tree-argmax, nibble-packed backptrs -----
// Tournament argmax with LEFT preference: on ties the smaller prev-tag index wins,
// bit-exactly matching jnp.argmax first-max semantics.
__global__ void viterbi_kernel(const float* __restrict__ trans, float* __restrict__ out,
                               int out_size) {
    __shared__ uint32_t bp[TT][2];
    int j = threadIdx.x;  // 32 lanes, j<16 active tags
    float tr[16];
#pragma unroll
    for (int p = 0; p < 16; p++) tr[p] = (j < 16) ? trans[j * 16 + p] : NEGV;
    float tstop = (j < 16) ? trans[STOP_TAG * 16 + j] : NEGV;
    float fv = (j == START_TAG) ? 0.f : NEGV;
    for (int t = 0; t < TT; t++) {
        float feat = (j < 16) ? g_feats[t * 16 + j] : 0.f;
        float v[16];
        int ix[16];
#pragma unroll
        for (int p = 0; p < 16; p++) {
            v[p] = __shfl_sync(0xFFFFFFFFu, fv, p) + tr[p];
            ix[p] = p;
        }
#pragma unroll
        for (int stp = 1; stp < 16; stp <<= 1) {
#pragma unroll
            for (int i = 0; i < 16; i += 2 * stp) {
                if (v[i + stp] > v[i]) { v[i] = v[i + stp]; ix[i] = ix[i + stp]; }
            }
        }
        float best = v[0];
        int arg = ix[0];
        fv = best + feat;
        uint32_t w0 = __reduce_or_sync(0xFFFFFFFFu, (j < 8) ? ((uint32_t)arg << (4 * j)) : 0u);
        uint32_t w1 = __reduce_or_sync(0xFFFFFFFFu,
                                       (j >= 8 && j < 16) ? ((uint32_t)arg << (4 * (j - 8))) : 0u);
        if (j == 0) { bp[t][0] = w0; bp[t][1] = w1; }
    }
    float tv = fv + tstop;
    float score = -3.4e38f;
    int tag = 0;
#pragma unroll
    for (int p = 0; p < 16; p++) {
        float c = __shfl_sync(0xFFFFFFFFu, tv, p);
        if (c > score) { score = c; tag = p; }
    }
    if (j == 0) {
        if (out_size >= TT + 1) {
            out[0] = score;
            for (int t = TT - 1; t >= 0; t--) {
                out[1 + t] = (float)tag;
                uint32_t w = bp[t][tag >> 3];
                tag = (int)((w >> (4 * (tag & 7))) & 15u);
            }
        } else if (out_size == TT) {
            for (int t = TT - 1; t >= 0; t--) {
                out[t] = (float)tag;
                uint32_t w = bp[t][tag >> 3];
                tag = (int)((w >> (4 * (tag & 7))) & 15u);
            }
        } else {
            out[0] = score;
        }
    }
}

// ---------------- launch ----------------
extern "C" void kernel_launch(void* const* d_in, const int* in_sizes, int n_in,
                              void* d_out, int out_size) {
    const int* sentence = (const int*)d_in[0];
    const float* emb    = (const float*)d_in[1];
    const float* Wih_f  = (const float*)d_in[2];
    const float* Whh_f  = (const float*)d_in[3];
    const float* bih_f  = (const float*)d_in[4];
    const float* bhh_f  = (const float*)d_in[5];
    const float* Wih_b  = (const float*)d_in[6];
    const float* Whh_b  = (const float*)d_in[7];
    const float* bih_b  = (const float*)d_in[8];
    const float* bhh_b  = (const float*)d_in[9];
    const float* h0     = (const float*)d_in[10];
    const float* c0     = (const float*)d_in[11];
    const float* w_omega = (const float*)d_in[12];
    const float* u_omega = (const float*)d_in[13];
    const float* W_tag  = (const float*)d_in[14];
    const float* b_tag  = (const float*)d_in[15];
    const float* trans  = (const float*)d_in[16];

    gather_emb<<<TT, EE>>>(sentence, emb);
    gemm_nt_bias<<<dim3(16, 64, 2), 256>>>(Wih_f, Wih_b, bih_f, bhh_f, bih_b, bhh_b);
    lstm_kernel<<<16, 512>>>(Whh_f, Whh_b, h0, c0);
    gemm_nn_tanh<<<dim3(8, 64), 256>>>(w_omega);
    logits_kernel<<<TT, 256>>>(u_omega);
    softmax_kernel<<<1, 1024>>>();
    feats_kernel<<<TT, HH>>>(W_tag, b_tag);
    viterbi_kernel<<<1, 32>>>(trans, (float*)d_out, out_size);
}

// round 16
// speedup vs baseline: 1.0761x; 1.0761x over previous
#include <cuda_runtime.h>
#include <cstdint>

#define TT 4096
#define EE 256
#define HD 256
#define HH 512
#define NT 16
#define START_TAG 14
#define STOP_TAG 15
#define NEGV -10000.0f

// ---------------- scratch (static __device__, no allocation) ----------------
__device__ float g_x[TT * EE];            // gathered embeddings [T,E]
__device__ float g_Xp[2][TT * 1024];      // x@Wih^T + bih + bhh per dir  [T,1024]
__device__ float g_hid[TT * HH];          // [T,512] concat(hf,hb)
__device__ float g_tmp[TT * HH];          // tanh(hid @ w_omega)
__device__ float g_logits[TT];
__device__ float g_alpha[TT];
__device__ float g_feats[TT * NT];

// ---------------- helpers ----------------
__device__ __forceinline__ unsigned long long ffma2(unsigned long long a,
                                                    unsigned long long b,
                                                    unsigned long long c) {
    unsigned long long d;
    asm("fma.rn.f32x2 %0, %1, %2, %3;" : "=l"(d) : "l"(a), "l"(b), "l"(c));
    return d;
}
__device__ __forceinline__ float2 unpack2(unsigned long long a) {
    float2 u;
    asm("mov.b64 {%0,%1}, %2;" : "=f"(u.x), "=f"(u.y) : "l"(a));
    return u;
}
__device__ __forceinline__ uint32_t smem_u32(const void* p) {
    return (uint32_t)__cvta_generic_to_shared(p);
}
__device__ __forceinline__ void cluster_sync_all() {
    asm volatile("barrier.cluster.arrive.aligned;" ::: "memory");
    asm volatile("barrier.cluster.wait.aligned;" ::: "memory");
}
__device__ __forceinline__ void st_cluster_f32(uint32_t laddr, int peer, float v) {
    asm volatile(
        "{\n\t.reg .u32 ra;\n\t"
        "mapa.shared::cluster.u32 ra, %0, %1;\n\t"
        "st.shared::cluster.f32 [ra], %2;\n\t}"
        :: "r"(laddr), "r"(peer), "f"(v) : "memory");
}
// hardware tanh: single MUFU.TANH (sm_75+), abs err ~2^-11
__device__ __forceinline__ float mufu_tanh(float x) {
    float y;
    asm("tanh.approx.f32 %0, %1;" : "=f"(y) : "f"(x));
    return y;
}
// sigmoid via hardware tanh: 1 MUFU + 1 FFMA
__device__ __forceinline__ float mufu_sigmoid(float x) {
    return fmaf(0.5f, mufu_tanh(0.5f * x), 0.5f);
}

// ---------------- 1. gather embeddings ----------------
__global__ void gather_emb(const int* __restrict__ sent, const float* __restrict__ emb) {
    int t = blockIdx.x;
    int e = threadIdx.x;
    g_x[t * EE + e] = emb[(size_t)sent[t] * EE + e];
}

// ---------------- 2. input projection: Xp = X @ Wih^T + bih + bhh ----------------
#define BM 64
#define BN 64
#define BK 16
__global__ void gemm_nt_bias(const float* __restrict__ Wf, const float* __restrict__ Wb,
                             const float* __restrict__ bihf, const float* __restrict__ bhhf,
                             const float* __restrict__ bihb, const float* __restrict__ bhhb) {
    const int dir = blockIdx.z;
    const float* B = dir ? Wb : Wf;
    const float* b1 = dir ? bihb : bihf;
    const float* b2 = dir ? bhhb : bhhf;
    float* C = g_Xp[dir];
    const float* A = g_x;
    const int K = EE, N = 1024;
    __shared__ float As[BK][BM + 4];
    __shared__ float Bs[BK][BN + 4];
    int tid = threadIdx.x;
    int tx = tid & 15, ty = tid >> 4;
    int by = blockIdx.y * BM, bx = blockIdx.x * BN;
    float acc[4][4] = {};
    for (int k0 = 0; k0 < K; k0 += BK) {
#pragma unroll
        for (int l = 0; l < 4; l++) {
            int e = tid + 256 * l;
            int m = e >> 4, kk = e & 15;
            As[kk][m] = A[(by + m) * K + k0 + kk];
            Bs[kk][m] = B[(bx + m) * K + k0 + kk];
        }
        __syncthreads();
#pragma unroll
        for (int kk = 0; kk < BK; kk++) {
            float ra[4], rb[4];
#pragma unroll
            for (int i = 0; i < 4; i++) ra[i] = As[kk][ty * 4 + i];
#pragma unroll
            for (int j = 0; j < 4; j++) rb[j] = Bs[kk][tx * 4 + j];
#pragma unroll
            for (int i = 0; i < 4; i++)
#pragma unroll
                for (int j = 0; j < 4; j++) acc[i][j] = fmaf(ra[i], rb[j], acc[i][j]);
        }
        __syncthreads();
    }
#pragma unroll
    for (int j = 0; j < 4; j++) {
        int c = bx + tx * 4 + j;
        float bb = b1[c] + b2[c];
#pragma unroll
        for (int i = 0; i < 4; i++)
            C[(size_t)(by + ty * 4 + i) * N + c] = acc[i][j] + bb;
    }
}

// ---------------- 3. LSTM recurrence: 2 clusters of 8 CTAs (R13 structure) ----------
// CTA (rank r, dir d) owns hidden units [r*32, r*32+32).
// Matvec: 512 threads, lr = tid>>2 = local gate row (gate = lr>>5, unit = lr&31),
// q = tid&3 covers k-pairs q+4i (conflict-free LDS.64, 4-way broadcast).
// Activation: warp0 lane t owns unit uu = crank*32 + t; MUFU.TANH-based
// activations (~12 instrs vs ~50 for EX2 chains). cluster.sync per step (frozen).
__global__ void __cluster_dims__(8, 1, 1) lstm_kernel(
    const float* __restrict__ Whh_f, const float* __restrict__ Whh_b,
    const float* __restrict__ h0, const float* __restrict__ c0) {
    __shared__ __align__(16) float hbuf[2][HD];
    __shared__ float gsh[128];
    const int tid = threadIdx.x;
    const int dir = blockIdx.x >> 3;
    uint32_t crank;
    asm("mov.u32 %0, %%cluster_ctarank;" : "=r"(crank));
    const int lr = tid >> 2, q = tid & 3;
    const int gi = lr >> 5, ul = lr & 31;
    const int u = (int)crank * 32 + ul;
    const int grow = gi * 256 + u;
    const int uu = (int)crank * 32 + tid;   // unit owned in activation phase (tid<32)
    const float* Whh = dir ? Whh_b : Whh_f;
    const float* Xp = g_Xp[dir];

    // preload weights: 32 f32x2 pairs, k-interleaved by q
    unsigned long long w2[32];
    const unsigned long long* wr = (const unsigned long long*)(Whh + (size_t)grow * HD);
#pragma unroll
    for (int i = 0; i < 32; i++) w2[i] = __ldg(wr + q + 4 * i);

    if (tid < HD) hbuf[0][tid] = h0[dir * HD + tid];
    float creg = 0.f;
    if (tid < 32) creg = c0[dir * HD + uu];
    __syncthreads();
    cluster_sync_all();   // initial hbuf visible cluster-wide

    for (int s = 0; s < TT; s++) {
        int tg = dir ? (TT - 1 - s) : s;
        float xg = __ldg(&Xp[(size_t)tg * 1024 + grow]);
        int buf = s & 1;
        const unsigned long long* hb = (const unsigned long long*)hbuf[buf];
        unsigned long long a0 = 0, a1 = 0;
#pragma unroll
        for (int i = 0; i < 32; i += 2) {
            a0 = ffma2(w2[i], hb[q + 4 * i], a0);
            a1 = ffma2(w2[i + 1], hb[q + 4 * (i + 1)], a1);
        }
        float2 f0 = unpack2(a0), f1 = unpack2(a1);
        float acc = (f0.x + f0.y) + (f1.x + f1.y);
        acc += __shfl_down_sync(0xFFFFFFFFu, acc, 2);
        acc += __shfl_down_sync(0xFFFFFFFFu, acc, 1);
        if (q == 0) gsh[lr] = acc + xg;
        __syncthreads();
        if (tid < 32) {
            float vi = gsh[tid], vf = gsh[32 + tid], vg = gsh[64 + tid], vo = gsh[96 + tid];
            float si = mufu_sigmoid(vi);
            float sf = mufu_sigmoid(vf);
            float so = mufu_sigmoid(vo);
            creg = sf * creg + si * mufu_tanh(vg);
            float h = so * mufu_tanh(creg);
            uint32_t dst = smem_u32(&hbuf[buf ^ 1][uu]);
#pragma unroll
            for (int peer = 0; peer < 8; peer++) st_cluster_f32(dst, peer, h);
            g_hid[(size_t)tg * HH + dir * HD + uu] = h;
        }
        cluster_sync_all();
    }
}

// ---------------- 4. attention GEMM: tmp = tanh(hid @ w_omega) ----------------
__global__ void gemm_nn_tanh(const float* __restrict__ B) {
    const float* A = g_hid;
    float* C = g_tmp;
    const int K = HH, N = HH;
    __shared__ float As[BK][BM + 4];
    __shared__ float Bs[BK][BN + 4];
    int tid = threadIdx.x;
    int tx = tid & 15, ty = tid >> 4;
    int by = blockIdx.y * BM, bx = blockIdx.x * BN;
    float acc[4][4] = {};
    for (int k0 = 0; k0 < K; k0 += BK) {
#pragma unroll
        for (int l = 0; l < 4; l++) {
            int e = tid + 256 * l;
            int m = e >> 4, kk = e & 15;
            As[kk][m] = A[(size_t)(by + m) * K + k0 + kk];
            int n = e & 63, kb = e >> 6;
            Bs[kb][n] = B[(size_t)(k0 + kb) * N + bx + n];
        }
        __syncthreads();
#pragma unroll
        for (int kk = 0; kk < BK; kk++) {
            float ra[4], rb[4];
#pragma unroll
            for (int i = 0; i < 4; i++) ra[i] = As[kk][ty * 4 + i];
#pragma unroll
            for (int j = 0; j < 4; j++) rb[j] = Bs[kk][tx * 4 + j];
#pragma unroll
            for (int i = 0; i < 4; i++)
#pragma unroll
                for (int j = 0; j < 4; j++) acc[i][j] = fmaf(ra[i], rb[j], acc[i][j]);
        }
        __syncthreads();
    }
#pragma unroll
    for (int i = 0; i < 4; i++)
#pragma unroll
        for (int j = 0; j < 4; j++)
            C[(size_t)(by + ty * 4 + i) * N + bx + tx * 4 + j] = mufu_tanh(acc[i][j]);
}

// ---------------- 5. logits[t] = tmp[t,:] . u_omega ----------------
__global__ void logits_kernel(const float* __restrict__ u_omega) {
    int t = blockIdx.x;
    int tid = threadIdx.x;  // 256
    float p = g_tmp[(size_t)t * HH + tid] * u_omega[tid]
            + g_tmp[(size_t)t * HH + 256 + tid] * u_omega[256 + tid];
#pragma unroll
    for (int o = 16; o; o >>= 1) p += __shfl_down_sync(0xFFFFFFFFu, p, o);
    __shared__ float ws[8];
    if ((tid & 31) == 0) ws[tid >> 5] = p;
    __syncthreads();
    if (tid < 8) {
        float v = ws[tid];
#pragma unroll
        for (int o = 4; o; o >>= 1) v += __shfl_down_sync(0xFFu, v, o);
        if (tid == 0) g_logits[t] = v;
    }
}

// ---------------- 6. softmax over T ----------------
__global__ void softmax_kernel() {
    __shared__ float red[32];
    __shared__ float red2[32];
    int tid = threadIdx.x;  // 1024
    float m = -3.4e38f;
    for (int t = tid; t < TT; t += 1024) m = fmaxf(m, g_logits[t]);
#pragma unroll
    for (int o = 16; o; o >>= 1) m = fmaxf(m, __shfl_xor_sync(0xFFFFFFFFu, m, o));
    if ((tid & 31) == 0) red[tid >> 5] = m;
    __syncthreads();
    if (tid < 32) {
        float v = red[tid];
#pragma unroll
        for (int o = 16; o; o >>= 1) v = fmaxf(v, __shfl_xor_sync(0xFFFFFFFFu, v, o));
        red[tid] = v;
    }
    __syncthreads();
    m = red[0];
    float s = 0.f;
    for (int t = tid; t < TT; t += 1024) {
        float e = expf(g_logits[t] - m);
        g_alpha[t] = e;
        s += e;
    }
#pragma unroll
    for (int o = 16; o; o >>= 1) s += __shfl_xor_sync(0xFFFFFFFFu, s, o);
    if ((tid & 31) == 0) red2[tid >> 5] = s;
    __syncthreads();
    if (tid < 32) {
        float v = red2[tid];
#pragma unroll
        for (int o = 16; o; o >>= 1) v += __shfl_xor_sync(0xFFFFFFFFu, v, o);
        red2[tid] = v;
    }
    __syncthreads();
    float inv = 1.f / red2[0];
    for (int t = tid; t < TT; t += 1024) g_alpha[t] *= inv;
}

// ---------------- 7. feats = (alpha*hid) @ W_tag^T + b_tag ----------------
__global__ void feats_kernel(const float* __restrict__ Wtag, const float* __restrict__ btag) {
    int t = blockIdx.x;
    int tid = threadIdx.x;  // 512
    __shared__ float s[HH];
    float al = g_alpha[t];
    s[tid] = g_hid[(size_t)t * HH + tid] * al;
    __syncthreads();
    int w = tid >> 5, lane = tid & 31;  // 16 warps = 16 tags
    float acc = 0.f;
    const float* wt = Wtag + w * HH;
#pragma unroll 4
    for (int k = lane; k < HH; k += 32) acc = fmaf(s[k], wt[k], acc);
#pragma unroll
    for (int o = 16; o; o >>= 1) acc += __shfl_down_sync(0xFFFFFFFFu, acc, o);
    if (lane == 0) g_feats[t * NT + w] = acc + btag[w];
}

// ---------------- 8. Viterbi: single warp, tree-argmax, nibble-packed backptrs -----
// Tournament argmax with LEFT preference: on ties the smaller prev-tag index wins,
// bit-exactly matching jnp.argmax first-max semantics.
__global__ void viterbi_kernel(const float* __restrict__ trans, float* __restrict__ out,
                               int out_size) {
    __shared__ uint32_t bp[TT][2];
    int j = threadIdx.x;  // 32 lanes, j<16 active tags
    float tr[16];
#pragma unroll
    for (int p = 0; p < 16; p++) tr[p] = (j < 16) ? trans[j * 16 + p] : NEGV;
    float tstop = (j < 16) ? trans[STOP_TAG * 16 + j] : NEGV;
    float fv = (j == START_TAG) ? 0.f : NEGV;
    for (int t = 0; t < TT; t++) {
        float feat = (j < 16) ? g_feats[t * 16 + j] : 0.f;
        float v[16];
        int ix[16];
#pragma unroll
        for (int p = 0; p < 16; p++) {
            v[p] = __shfl_sync(0xFFFFFFFFu, fv, p) + tr[p];
            ix[p] = p;
        }
#pragma unroll
        for (int stp = 1; stp < 16; stp <<= 1) {
#pragma unroll
            for (int i = 0; i < 16; i += 2 * stp) {
                if (v[i + stp] > v[i]) { v[i] = v[i + stp]; ix[i] = ix[i + stp]; }
            }
        }
        float best = v[0];
        int arg = ix[0];
        fv = best + feat;
        uint32_t w0 = __reduce_or_sync(0xFFFFFFFFu, (j < 8) ? ((uint32_t)arg << (4 * j)) : 0u);
        uint32_t w1 = __reduce_or_sync(0xFFFFFFFFu,
                                       (j >= 8 && j < 16) ? ((uint32_t)arg << (4 * (j - 8))) : 0u);
        if (j == 0) { bp[t][0] = w0; bp[t][1] = w1; }
    }
    float tv = fv + tstop;
    float score = -3.4e38f;
    int tag = 0;
#pragma unroll
    for (int p = 0; p < 16; p++) {
        float c = __shfl_sync(0xFFFFFFFFu, tv, p);
        if (c > score) { score = c; tag = p; }
    }
    if (j == 0) {
        if (out_size >= TT + 1) {
            out[0] = score;
            for (int t = TT - 1; t >= 0; t--) {
                out[1 + t] = (float)tag;
                uint32_t w = bp[t][tag >> 3];
                tag = (int)((w >> (4 * (tag & 7))) & 15u);
            }
        } else if (out_size == TT) {
            for (int t = TT - 1; t >= 0; t--) {
                out[t] = (float)tag;
                uint32_t w = bp[t][tag >> 3];
                tag = (int)((w >> (4 * (tag & 7))) & 15u);
            }
        } else {
            out[0] = score;
        }
    }
}

// ---------------- launch ----------------
extern "C" void kernel_launch(void* const* d_in, const int* in_sizes, int n_in,
                              void* d_out, int out_size) {
    const int* sentence = (const int*)d_in[0];
    const float* emb    = (const float*)d_in[1];
    const float* Wih_f  = (const float*)d_in[2];
    const float* Whh_f  = (const float*)d_in[3];
    const float* bih_f  = (const float*)d_in[4];
    const float* bhh_f  = (const float*)d_in[5];
    const float* Wih_b  = (const float*)d_in[6];
    const float* Whh_b  = (const float*)d_in[7];
    const float* bih_b  = (const float*)d_in[8];
    const float* bhh_b  = (const float*)d_in[9];
    const float* h0     = (const float*)d_in[10];
    const float* c0     = (const float*)d_in[11];
    const float* w_omega = (const float*)d_in[12];
    const float* u_omega = (const float*)d_in[13];
    const float* W_tag  = (const float*)d_in[14];
    const float* b_tag  = (const float*)d_in[15];
    const float* trans  = (const float*)d_in[16];

    gather_emb<<<TT, EE>>>(sentence, emb);
    gemm_nt_bias<<<dim3(16, 64, 2), 256>>>(Wih_f, Wih_b, bih_f, bhh_f, bih_b, bhh_b);
    lstm_kernel<<<16, 512>>>(Whh_f, Whh_b, h0, c0);
    gemm_nn_tanh<<<dim3(8, 64), 256>>>(w_omega);
    logits_kernel<<<TT, 256>>>(u_omega);
    softmax_kernel<<<1, 1024>>>();
    feats_kernel<<<TT, HH>>>(W_tag, b_tag);
    viterbi_kernel<<<1, 32>>>(trans, (float*)d_out, out_size);
}

// round 17
// speedup vs baseline: 1.1210x; 1.0417x over previous
#include <cuda_runtime.h>
#include <cstdint>

#define TT 4096
#define EE 256
#define HD 256
#define HH 512
#define NT 16
#define START_TAG 14
#define STOP_TAG 15
#define NEGV -10000.0f

// ---------------- scratch (static __device__, no allocation) ----------------
__device__ float g_x[TT * EE];            // gathered embeddings [T,E]
__device__ float g_Xp[2][TT * 1024];      // x@Wih^T + bih + bhh per dir  [T,1024]
__device__ float g_hid[TT * HH];          // [T,512] concat(hf,hb)
__device__ float g_tmp[TT * HH];          // tanh(hid @ w_omega)
__device__ float g_logits[TT];
__device__ float g_alpha[TT];
__device__ float g_feats[TT * NT];

// ---------------- helpers ----------------
__device__ __forceinline__ unsigned long long ffma2(unsigned long long a,
                                                    unsigned long long b,
                                                    unsigned long long c) {
    unsigned long long d;
    asm("fma.rn.f32x2 %0, %1, %2, %3;" : "=l"(d) : "l"(a), "l"(b), "l"(c));
    return d;
}
__device__ __forceinline__ float2 unpack2(unsigned long long a) {
    float2 u;
    asm("mov.b64 {%0,%1}, %2;" : "=f"(u.x), "=f"(u.y) : "l"(a));
    return u;
}
__device__ __forceinline__ uint32_t smem_u32(const void* p) {
    return (uint32_t)__cvta_generic_to_shared(p);
}
__device__ __forceinline__ void cluster_arrive() {
    asm volatile("barrier.cluster.arrive.aligned;" ::: "memory");
}
__device__ __forceinline__ void cluster_wait() {
    asm volatile("barrier.cluster.wait.aligned;" ::: "memory");
}
__device__ __forceinline__ void cluster_sync_all() {
    cluster_arrive();
    cluster_wait();
}
__device__ __forceinline__ uint32_t mapa_sh(uint32_t laddr, int peer) {
    uint32_t r;
    asm("mapa.shared::cluster.u32 %0, %1, %2;" : "=r"(r) : "r"(laddr), "r"(peer));
    return r;
}
__device__ __forceinline__ void st_cluster_addr(uint32_t addr, float v) {
    asm volatile("st.shared::cluster.f32 [%0], %1;" :: "r"(addr), "f"(v) : "memory");
}
// hardware tanh: single MUFU.TANH (sm_75+), abs err ~2^-11
__device__ __forceinline__ float mufu_tanh(float x) {
    float y;
    asm("tanh.approx.f32 %0, %1;" : "=f"(y) : "f"(x));
    return y;
}
// sigmoid via hardware tanh: 1 MUFU + 1 FFMA
__device__ __forceinline__ float mufu_sigmoid(float x) {
    return fmaf(0.5f, mufu_tanh(0.5f * x), 0.5f);
}

// ---------------- 1. gather embeddings ----------------
__global__ void gather_emb(const int* __restrict__ sent, const float* __restrict__ emb) {
    int t = blockIdx.x;
    int e = threadIdx.x;
    g_x[t * EE + e] = emb[(size_t)sent[t] * EE + e];
}

// ---------------- 2. input projection: Xp = X @ Wih^T + bih + bhh ----------------
#define BM 64
#define BN 64
#define BK 16
__global__ void gemm_nt_bias(const float* __restrict__ Wf, const float* __restrict__ Wb,
                             const float* __restrict__ bihf, const float* __restrict__ bhhf,
                             const float* __restrict__ bihb, const float* __restrict__ bhhb) {
    const int dir = blockIdx.z;
    const float* B = dir ? Wb : Wf;
    const float* b1 = dir ? bihb : bihf;
    const float* b2 = dir ? bhhb : bhhf;
    float* C = g_Xp[dir];
    const float* A = g_x;
    const int K = EE, N = 1024;
    __shared__ float As[BK][BM + 4];
    __shared__ float Bs[BK][BN + 4];
    int tid = threadIdx.x;
    int tx = tid & 15, ty = tid >> 4;
    int by = blockIdx.y * BM, bx = blockIdx.x * BN;
    float acc[4][4] = {};
    for (int k0 = 0; k0 < K; k0 += BK) {
#pragma unroll
        for (int l = 0; l < 4; l++) {
            int e = tid + 256 * l;
            int m = e >> 4, kk = e & 15;
            As[kk][m] = A[(by + m) * K + k0 + kk];
            Bs[kk][m] = B[(bx + m) * K + k0 + kk];
        }
        __syncthreads();
#pragma unroll
        for (int kk = 0; kk < BK; kk++) {
            float ra[4], rb[4];
#pragma unroll
            for (int i = 0; i < 4; i++) ra[i] = As[kk][ty * 4 + i];
#pragma unroll
            for (int j = 0; j < 4; j++) rb[j] = Bs[kk][tx * 4 + j];
#pragma unroll
            for (int i = 0; i < 4; i++)
#pragma unroll
                for (int j = 0; j < 4; j++) acc[i][j] = fmaf(ra[i], rb[j], acc[i][j]);
        }
        __syncthreads();
    }
#pragma unroll
    for (int j = 0; j < 4; j++) {
        int c = bx + tx * 4 + j;
        float bb = b1[c] + b2[c];
#pragma unroll
        for (int i = 0; i < 4; i++)
            C[(size_t)(by + ty * 4 + i) * N + c] = acc[i][j] + bb;
    }
}

// ---------------- 3. LSTM recurrence: 2 clusters of 8 CTAs --------------------------
// R16 structure with three critical-path micro-cuts:
//  - mapa peer addresses hoisted to prologue (both buffer parities)
//  - split barrier: stores -> arrive -> {g_hid store, next xg prefetch} -> wait
//    (the prefetch lands during the ~490cyc barrier wait, so the post-IVALL
//     L1-miss never exposes; NOT the R7 mistake: load sits in a dead region)
__global__ void __cluster_dims__(8, 1, 1) lstm_kernel(
    const float* __restrict__ Whh_f, const float* __restrict__ Whh_b,
    const float* __restrict__ h0, const float* __restrict__ c0) {
    __shared__ __align__(16) float hbuf[2][HD];
    __shared__ float gsh[128];
    const int tid = threadIdx.x;
    const int dir = blockIdx.x >> 3;
    uint32_t crank;
    asm("mov.u32 %0, %%cluster_ctarank;" : "=r"(crank));
    const int lr = tid >> 2, q = tid & 3;
    const int gi = lr >> 5, ul = lr & 31;
    const int u = (int)crank * 32 + ul;
    const int grow = gi * 256 + u;
    const int uu = (int)crank * 32 + tid;   // unit owned in activation phase (tid<32)
    const float* Whh = dir ? Whh_b : Whh_f;
    const float* Xp = g_Xp[dir];

    // preload weights: 32 f32x2 pairs, k-interleaved by q
    unsigned long long w2[32];
    const unsigned long long* wr = (const unsigned long long*)(Whh + (size_t)grow * HD);
#pragma unroll
    for (int i = 0; i < 32; i++) w2[i] = __ldg(wr + q + 4 * i);

    // hoisted DSMEM peer addresses for both parities (warp0 only uses them)
    uint32_t dstA[8], dstB[8];   // A: write hbuf[1] (buf==0), B: write hbuf[0] (buf==1)
    {
        uint32_t l1 = smem_u32(&hbuf[1][uu & 31]);
        uint32_t l0 = smem_u32(&hbuf[0][uu & 31]);
#pragma unroll
        for (int p = 0; p < 8; p++) {
            dstA[p] = mapa_sh(l1, p);
            dstB[p] = mapa_sh(l0, p);
        }
    }
    // note: address base uses local unit index (uu&31 == tid for tid<32); the
    // mapa'd address points at peer CTA's hbuf[*][crank*32+tid]? NO — peer's
    // hbuf[*][tid] local slot. Must offset by crank*32 within the buffer:
    // recompute correctly below (overwrite).
    {
        uint32_t l1 = smem_u32(&hbuf[1][0]) + (uint32_t)(((int)crank * 32 + tid) * 4);
        uint32_t l0 = smem_u32(&hbuf[0][0]) + (uint32_t)(((int)crank * 32 + tid) * 4);
#pragma unroll
        for (int p = 0; p < 8; p++) {
            dstA[p] = mapa_sh(l1, p);
            dstB[p] = mapa_sh(l0, p);
        }
    }

    if (tid < HD) hbuf[0][tid] = h0[dir * HD + tid];
    float creg = 0.f;
    if (tid < 32) creg = c0[dir * HD + uu];
    __syncthreads();
    cluster_sync_all();   // initial hbuf visible cluster-wide

    float xg = __ldg(&Xp[(size_t)(dir ? (TT - 1) : 0) * 1024 + grow]);

    for (int s = 0; s < TT; s++) {
        int tg = dir ? (TT - 1 - s) : s;
        int buf = s & 1;
        const unsigned long long* hb = (const unsigned long long*)hbuf[buf];
        unsigned long long a0 = 0, a1 = 0;
#pragma unroll
        for (int i = 0; i < 32; i += 2) {
            a0 = ffma2(w2[i], hb[q + 4 * i], a0);
            a1 = ffma2(w2[i + 1], hb[q + 4 * (i + 1)], a1);
        }
        float2 f0 = unpack2(a0), f1 = unpack2(a1);
        float acc = (f0.x + f0.y) + (f1.x + f1.y);
        acc += __shfl_down_sync(0xFFFFFFFFu, acc, 2);
        acc += __shfl_down_sync(0xFFFFFFFFu, acc, 1);
        if (q == 0) gsh[lr] = acc + xg;
        __syncthreads();
        float h = 0.f;
        if (tid < 32) {
            float vi = gsh[tid], vf = gsh[32 + tid], vg = gsh[64 + tid], vo = gsh[96 + tid];
            float si = mufu_sigmoid(vi);
            float sf = mufu_sigmoid(vf);
            float so = mufu_sigmoid(vo);
            creg = sf * creg + si * mufu_tanh(vg);
            h = so * mufu_tanh(creg);
            if (buf == 0) {
#pragma unroll
                for (int p = 0; p < 8; p++) st_cluster_addr(dstA[p], h);
            } else {
#pragma unroll
                for (int p = 0; p < 8; p++) st_cluster_addr(dstB[p], h);
            }
        }
        cluster_arrive();
        // dead window while barrier propagates: do off-path work
        if (tid < 32) g_hid[(size_t)tg * HH + dir * HD + uu] = h;
        if (s < TT - 1) {
            int tgn = dir ? (tg - 1) : (tg + 1);
            xg = __ldg(&Xp[(size_t)tgn * 1024 + grow]);
        }
        cluster_wait();
    }
    cluster_sync_all();   // teardown: keep DSMEM valid until all CTAs done
}

// ---------------- 4. attention GEMM: tmp = tanh(hid @ w_omega) ----------------
__global__ void gemm_nn_tanh(const float* __restrict__ B) {
    const float* A = g_hid;
    float* C = g_tmp;
    const int K = HH, N = HH;
    __shared__ float As[BK][BM + 4];
    __shared__ float Bs[BK][BN + 4];
    int tid = threadIdx.x;
    int tx = tid & 15, ty = tid >> 4;
    int by = blockIdx.y * BM, bx = blockIdx.x * BN;
    float acc[4][4] = {};
    for (int k0 = 0; k0 < K; k0 += BK) {
#pragma unroll
        for (int l = 0; l < 4; l++) {
            int e = tid + 256 * l;
            int m = e >> 4, kk = e & 15;
            As[kk][m] = A[(size_t)(by + m) * K + k0 + kk];
            int n = e & 63, kb = e >> 6;
            Bs[kb][n] = B[(size_t)(k0 + kb) * N + bx + n];
        }
        __syncthreads();
#pragma unroll
        for (int kk = 0; kk < BK; kk++) {
            float ra[4], rb[4];
#pragma unroll
            for (int i = 0; i < 4; i++) ra[i] = As[kk][ty * 4 + i];
#pragma unroll
            for (int j = 0; j < 4; j++) rb[j] = Bs[kk][tx * 4 + j];
#pragma unroll
            for (int i = 0; i < 4; i++)
#pragma unroll
                for (int j = 0; j < 4; j++) acc[i][j] = fmaf(ra[i], rb[j], acc[i][j]);
        }
        __syncthreads();
    }
#pragma unroll
    for (int i = 0; i < 4; i++)
#pragma unroll
        for (int j = 0; j < 4; j++)
            C[(size_t)(by + ty * 4 + i) * N + bx + tx * 4 + j] = mufu_tanh(acc[i][j]);
}

// ---------------- 5. logits[t] = tmp[t,:] . u_omega ----------------
__global__ void logits_kernel(const float* __restrict__ u_omega) {
    int t = blockIdx.x;
    int tid = threadIdx.x;  // 256
    float p = g_tmp[(size_t)t * HH + tid] * u_omega[tid]
            + g_tmp[(size_t)t * HH + 256 + tid] * u_omega[256 + tid];
#pragma unroll
    for (int o = 16; o; o >>= 1) p += __shfl_down_sync(0xFFFFFFFFu, p, o);
    __shared__ float ws[8];
    if ((tid & 31) == 0) ws[tid >> 5] = p;
    __syncthreads();
    if (tid < 8) {
        float v = ws[tid];
#pragma unroll
        for (int o = 4; o; o >>= 1) v += __shfl_down_sync(0xFFu, v, o);
        if (tid == 0) g_logits[t] = v;
    }
}

// ---------------- 6. softmax over T ----------------
__global__ void softmax_kernel() {
    __shared__ float red[32];
    __shared__ float red2[32];
    int tid = threadIdx.x;  // 1024
    float m = -3.4e38f;
    for (int t = tid; t < TT; t += 1024) m = fmaxf(m, g_logits[t]);
#pragma unroll
    for (int o = 16; o; o >>= 1) m = fmaxf(m, __shfl_xor_sync(0xFFFFFFFFu, m, o));
    if ((tid & 31) == 0) red[tid >> 5] = m;
    __syncthreads();
    if (tid < 32) {
        float v = red[tid];
#pragma unroll
        for (int o = 16; o; o >>= 1) v = fmaxf(v, __shfl_xor_sync(0xFFFFFFFFu, v, o));
        red[tid] = v;
    }
    __syncthreads();
    m = red[0];
    float s = 0.f;
    for (int t = tid; t < TT; t += 1024) {
        float e = expf(g_logits[t] - m);
        g_alpha[t] = e;
        s += e;
    }
#pragma unroll
    for (int o = 16; o; o >>= 1) s += __shfl_xor_sync(0xFFFFFFFFu, s, o);
    if ((tid & 31) == 0) red2[tid >> 5] = s;
    __syncthreads();
    if (tid < 32) {
        float v = red2[tid];
#pragma unroll
        for (int o = 16; o; o >>= 1) v += __shfl_xor_sync(0xFFFFFFFFu, v, o);
        red2[tid] = v;
    }
    __syncthreads();
    float inv = 1.f / red2[0];
    for (int t = tid; t < TT; t += 1024) g_alpha[t] *= inv;
}

// ---------------- 7. feats = (alpha*hid) @ W_tag^T + b_tag ----------------
__global__ void feats_kernel(const float* __restrict__ Wtag, const float* __restrict__ btag) {
    int t = blockIdx.x;
    int tid = threadIdx.x;  // 512
    __shared__ float s[HH];
    float al = g_alpha[t];
    s[tid] = g_hid[(size_t)t * HH + tid] * al;
    __syncthreads();
    int w = tid >> 5, lane = tid & 31;  // 16 warps = 16 tags
    float acc = 0.f;
    const float* wt = Wtag + w * HH;
#pragma unroll 4
    for (int k = lane; k < HH; k += 32) acc = fmaf(s[k], wt[k], acc);
#pragma unroll
    for (int o = 16; o; o >>= 1) acc += __shfl_down_sync(0xFFFFFFFFu, acc, o);
    if (lane == 0) g_feats[t * NT + w] = acc + btag[w];
}

// ---------------- 8. Viterbi: single warp, tree-argmax, nibble-packed backptrs -----
__global__ void viterbi_kernel(const float* __restrict__ trans, float* __restrict__ out,
                               int out_size) {
    __shared__ uint32_t bp[TT][2];
    int j = threadIdx.x;  // 32 lanes, j<16 active tags
    float tr[16];
#pragma unroll
    for (int p = 0; p < 16; p++) tr[p] = (j < 16) ? trans[j * 16 + p] : NEGV;
    float tstop = (j < 16) ? trans[STOP_TAG * 16 + j] : NEGV;
    float fv = (j == START_TAG) ? 0.f : NEGV;
    for (int t = 0; t < TT; t++) {
        float feat = (j < 16) ? g_feats[t * 16 + j] : 0.f;
        float v[16];
        int ix[16];
#pragma unroll
        for (int p = 0; p < 16; p++) {
            v[p] = __shfl_sync(0xFFFFFFFFu, fv, p) + tr[p];
            ix[p] = p;
        }
#pragma unroll
        for (int stp = 1; stp < 16; stp <<= 1) {
#pragma unroll
            for (int i = 0; i < 16; i += 2 * stp) {
                if (v[i + stp] > v[i]) { v[i] = v[i + stp]; ix[i] = ix[i + stp]; }
            }
        }
        float best = v[0];
        int arg = ix[0];
        fv = best + feat;
        uint32_t w0 = __reduce_or_sync(0xFFFFFFFFu, (j < 8) ? ((uint32_t)arg << (4 * j)) : 0u);
        uint32_t w1 = __reduce_or_sync(0xFFFFFFFFu,
                                       (j >= 8 && j < 16) ? ((uint32_t)arg << (4 * (j - 8))) : 0u);
        if (j == 0) { bp[t][0] = w0; bp[t][1] = w1; }
    }
    float tv = fv + tstop;
    float score = -3.4e38f;
    int tag = 0;
#pragma unroll
    for (int p = 0; p < 16; p++) {
        float c = __shfl_sync(0xFFFFFFFFu, tv, p);
        if (c > score) { score = c; tag = p; }
    }
    if (j == 0) {
        if (out_size >= TT + 1) {
            out[0] = score;
            for (int t = TT - 1; t >= 0; t--) {
                out[1 + t] = (float)tag;
                uint32_t w = bp[t][tag >> 3];
                tag = (int)((w >> (4 * (tag & 7))) & 15u);
            }
        } else if (out_size == TT) {
            for (int t = TT - 1; t >= 0; t--) {
                out[t] = (float)tag;
                uint32_t w = bp[t][tag >> 3];
                tag = (int)((w >> (4 * (tag & 7))) & 15u);
            }
        } else {
            out[0] = score;
        }
    }
}

// ---------------- launch ----------------
extern "C" void kernel_launch(void* const* d_in, const int* in_sizes, int n_in,
                              void* d_out, int out_size) {
    const int* sentence = (const int*)d_in[0];
    const float* emb    = (const float*)d_in[1];
    const float* Wih_f  = (const float*)d_in[2];
    const float* Whh_f  = (const float*)d_in[3];
    const float* bih_f  = (const float*)d_in[4];
    const float* bhh_f  = (const float*)d_in[5];
    const float* Wih_b  = (const float*)d_in[6];
    const float* Whh_b  = (const float*)d_in[7];
    const float* bih_b  = (const float*)d_in[8];
    const float* bhh_b  = (const float*)d_in[9];
    const float* h0     = (const float*)d_in[10];
    const float* c0     = (const float*)d_in[11];
    const float* w_omega = (const float*)d_in[12];
    const float* u_omega = (const float*)d_in[13];
    const float* W_tag  = (const float*)d_in[14];
    const float* b_tag  = (const float*)d_in[15];
    const float* trans  = (const float*)d_in[16];

    gather_emb<<<TT, EE>>>(sentence, emb);
    gemm_nt_bias<<<dim3(16, 64, 2), 256>>>(Wih_f, Wih_b, bih_f, bhh_f, bih_b, bhh_b);
    lstm_kernel<<<16, 512>>>(Whh_f, Whh_b, h0, c0);
    gemm_nn_tanh<<<dim3(8, 64), 256>>>(w_omega);
    logits_kernel<<<TT, 256>>>(u_omega);
    softmax_kernel<<<1, 1024>>>();
    feats_kernel<<<TT, HH>>>(W_tag, b_tag);
    viterbi_kernel<<<1, 32>>>(trans, (float*)d_out, out_size);
}